// round 3
// baseline (speedup 1.0000x reference)
#include <cuda_runtime.h>

// Problem constants
#define B_     2
#define C_     512
#define NSP    4096      // d*h*w = 16*16*16
#define NGR    32        // groups
#define CPG    16        // channels per group

// ---------------------------------------------------------------------------
// Scratch (device globals — no allocation allowed in kernel_launch)
// ---------------------------------------------------------------------------
__device__ float g_h[(size_t)B_ * C_ * NSP];
__device__ float g_q[(size_t)B_ * C_ * NSP];
__device__ float g_k[(size_t)B_ * C_ * NSP];
__device__ float g_v[(size_t)B_ * C_ * NSP];
__device__ float g_o[(size_t)B_ * C_ * NSP];
__device__ float g_attn[(size_t)B_ * NSP * NSP];   // 128 MB

// ---------------------------------------------------------------------------
// f32x2 packed helpers (FFMA2 path — 2x fp32 FMA throughput on sm_103a)
// ---------------------------------------------------------------------------
__device__ __forceinline__ void fma2(unsigned long long& d, unsigned long long a,
                                     unsigned long long b) {
    asm("fma.rn.f32x2 %0, %1, %2, %0;" : "+l"(d) : "l"(a), "l"(b));
}
__device__ __forceinline__ unsigned long long pack2(float x) {
    unsigned long long r;
    asm("mov.b64 %0, {%1, %1};" : "=l"(r) : "f"(x));
    return r;
}
__device__ __forceinline__ void unpack2(unsigned long long v, float& lo, float& hi) {
    asm("mov.b64 {%0, %1}, %2;" : "=f"(lo), "=f"(hi) : "l"(v));
}

// ---------------------------------------------------------------------------
// GroupNorm: one block per (batch, group). 16 channels * 4096 spatial each.
// ---------------------------------------------------------------------------
__global__ __launch_bounds__(256) void gn_kernel(const float* __restrict__ x,
                                                 const float* __restrict__ gamma,
                                                 const float* __restrict__ beta,
                                                 float* __restrict__ h) {
    int b = blockIdx.x >> 5;
    int g = blockIdx.x & 31;
    const size_t base = ((size_t)b * C_ + (size_t)g * CPG) * NSP;
    const float4* xp = (const float4*)(x + base);
    float4* hp = (float4*)(h + base);
    const int M4 = CPG * NSP / 4;   // 16384 float4
    int t = threadIdx.x;

    float s = 0.f, ss = 0.f;
    for (int i = t; i < M4; i += 256) {
        float4 v = xp[i];
        s  += v.x + v.y + v.z + v.w;
        ss += v.x * v.x + v.y * v.y + v.z * v.z + v.w * v.w;
    }
    __shared__ float sm[256], sm2[256];
    sm[t] = s; sm2[t] = ss;
    __syncthreads();
    for (int o = 128; o > 0; o >>= 1) {
        if (t < o) { sm[t] += sm[t + o]; sm2[t] += sm2[t + o]; }
        __syncthreads();
    }
    const float invM = 1.f / (float)(CPG * NSP);
    float mean = sm[0] * invM;
    float var  = sm2[0] * invM - mean * mean;
    float inv  = rsqrtf(var + 1e-6f);

    for (int i = t; i < M4; i += 256) {
        int ch = g * CPG + (i >> 10);        // 1024 float4 per channel
        float gam = gamma[ch] * inv;
        float bet = beta[ch] - mean * gam;
        float4 v = xp[i];
        v.x = v.x * gam + bet; v.y = v.y * gam + bet;
        v.z = v.z * gam + bet; v.w = v.w * gam + bet;
        hp[i] = v;
    }
}

// ---------------------------------------------------------------------------
// Row softmax over 4096 columns. One block (256 thr) per row, data in regs.
// ---------------------------------------------------------------------------
__global__ __launch_bounds__(256) void softmax_kernel(float* __restrict__ attn) {
    float4* p4 = (float4*)(attn + (size_t)blockIdx.x * NSP);
    int t = threadIdx.x;
    float4 v[4];
    float mx = -1e30f;
#pragma unroll
    for (int i = 0; i < 4; i++) {
        v[i] = p4[t + i * 256];
        mx = fmaxf(mx, fmaxf(fmaxf(v[i].x, v[i].y), fmaxf(v[i].z, v[i].w)));
    }
    __shared__ float sm[256];
    sm[t] = mx;
    __syncthreads();
    for (int o = 128; o > 0; o >>= 1) {
        if (t < o) sm[t] = fmaxf(sm[t], sm[t + o]);
        __syncthreads();
    }
    mx = sm[0];
    __syncthreads();

    float s = 0.f;
#pragma unroll
    for (int i = 0; i < 4; i++) {
        v[i].x = __expf(v[i].x - mx); v[i].y = __expf(v[i].y - mx);
        v[i].z = __expf(v[i].z - mx); v[i].w = __expf(v[i].w - mx);
        s += v[i].x + v[i].y + v[i].z + v[i].w;
    }
    sm[t] = s;
    __syncthreads();
    for (int o = 128; o > 0; o >>= 1) {
        if (t < o) sm[t] += sm[t + o];
        __syncthreads();
    }
    float r = 1.f / sm[0];
#pragma unroll
    for (int i = 0; i < 4; i++) {
        v[i].x *= r; v[i].y *= r; v[i].z *= r; v[i].w *= r;
        p4[t + i * 256] = v[i];
    }
}

// ---------------------------------------------------------------------------
// Generic tiled SGEMM, 128x128x16 tile, 256 threads, 8x8 per thread,
// inner loop in packed fma.rn.f32x2 (pairs along N).
//   C[m,n] = (sum_k A_l[m,k] * B_l[k,n]) ; A_l = TA ? A[k][m] : A[m][k]
//   EPI: 0=none, 1=+bias[m], 2=*alpha, 3=+bias[m]+resid[m,n]
// ---------------------------------------------------------------------------
template <bool TA, bool TB, int EPI>
__global__ __launch_bounds__(256) void gemm_kernel(
    const float* __restrict__ A, const float* __restrict__ B, float* __restrict__ Cc,
    int K, int lda, int ldb, int ldc,
    size_t sA, size_t sB, size_t sC,
    const float* __restrict__ bias, const float* __restrict__ resid, size_t sR,
    float alpha) {
    A  += (size_t)blockIdx.z * sA;
    B  += (size_t)blockIdx.z * sB;
    Cc += (size_t)blockIdx.z * sC;
    const float* R = (EPI == 3) ? (resid + (size_t)blockIdx.z * sR) : nullptr;

    __shared__ float As[16][132];
    __shared__ float Bs[16][132];

    int tid = threadIdx.x;
    int n0 = blockIdx.x * 128;
    int m0 = blockIdx.y * 128;
    int tx = tid & 15, ty = tid >> 4;
    int tn0 = tx * 8, tm0 = ty * 8;

    unsigned long long acc[8][4];
#pragma unroll
    for (int i = 0; i < 8; i++)
#pragma unroll
        for (int j = 0; j < 4; j++) acc[i][j] = 0ull;

    for (int k0 = 0; k0 < K; k0 += 16) {
#pragma unroll
        for (int it = 0; it < 2; it++) {
            int f = tid + it * 256;     // 512 float4 per operand tile
            if (!TA) {                   // A[m][k]: [128 x 16] tile, transpose into smem
                int row = f >> 2, kv = (f & 3) * 4;
                float4 v = *(const float4*)(A + (size_t)(m0 + row) * lda + k0 + kv);
                As[kv + 0][row] = v.x; As[kv + 1][row] = v.y;
                As[kv + 2][row] = v.z; As[kv + 3][row] = v.w;
            } else {                     // A[k][m]: [16 x 128] tile, direct
                int kk = f >> 5, mv = (f & 31) * 4;
                float4 v = *(const float4*)(A + (size_t)(k0 + kk) * lda + m0 + mv);
                *(float4*)&As[kk][mv] = v;
            }
            if (!TB) {                   // B[k][n]: [16 x 128] tile, direct
                int kk = f >> 5, nv = (f & 31) * 4;
                float4 v = *(const float4*)(B + (size_t)(k0 + kk) * ldb + n0 + nv);
                *(float4*)&Bs[kk][nv] = v;
            } else {                     // B[n][k]: [128 x 16] tile, transpose into smem
                int row = f >> 2, kv = (f & 3) * 4;
                float4 v = *(const float4*)(B + (size_t)(n0 + row) * ldb + k0 + kv);
                Bs[kv + 0][row] = v.x; Bs[kv + 1][row] = v.y;
                Bs[kv + 2][row] = v.z; Bs[kv + 3][row] = v.w;
            }
        }
        __syncthreads();

#pragma unroll
        for (int kk = 0; kk < 16; kk++) {
            float4 a0 = *(const float4*)&As[kk][tm0];
            float4 a1 = *(const float4*)&As[kk][tm0 + 4];
            const unsigned long long* bp = (const unsigned long long*)&Bs[kk][tn0];
            unsigned long long b2[4] = {bp[0], bp[1], bp[2], bp[3]};
            float av[8] = {a0.x, a0.y, a0.z, a0.w, a1.x, a1.y, a1.z, a1.w};
#pragma unroll
            for (int i = 0; i < 8; i++) {
                unsigned long long ad = pack2(av[i]);
#pragma unroll
                for (int j = 0; j < 4; j++) fma2(acc[i][j], ad, b2[j]);
            }
        }
        __syncthreads();
    }

#pragma unroll
    for (int i = 0; i < 8; i++) {
        int m = m0 + tm0 + i;
        float bv = (EPI == 1 || EPI == 3) ? bias[m] : 0.f;
        float out[8];
#pragma unroll
        for (int j = 0; j < 4; j++) {
            float lo, hi;
            unpack2(acc[i][j], lo, hi);
            if (EPI == 2) { lo *= alpha; hi *= alpha; }
            out[2 * j] = lo + bv;
            out[2 * j + 1] = hi + bv;
        }
        size_t off = (size_t)m * ldc + n0 + tn0;
        if (EPI == 3) {
#pragma unroll
            for (int j = 0; j < 8; j++) out[j] += R[off + j];
        }
        *(float4*)(Cc + off)     = make_float4(out[0], out[1], out[2], out[3]);
        *(float4*)(Cc + off + 4) = make_float4(out[4], out[5], out[6], out[7]);
    }
}

// ---------------------------------------------------------------------------
// Launch
// ---------------------------------------------------------------------------
extern "C" void kernel_launch(void* const* d_in, const int* in_sizes, int n_in,
                              void* d_out, int out_size) {
    (void)in_sizes; (void)n_in; (void)out_size;
    const float* x     = (const float*)d_in[0];
    const float* gamma = (const float*)d_in[1];
    const float* beta  = (const float*)d_in[2];
    const float* wq    = (const float*)d_in[3];
    const float* bq    = (const float*)d_in[4];
    const float* wk    = (const float*)d_in[5];
    const float* bk    = (const float*)d_in[6];
    const float* wv    = (const float*)d_in[7];
    const float* bv    = (const float*)d_in[8];
    const float* wo    = (const float*)d_in[9];
    const float* bo    = (const float*)d_in[10];
    float* out = (float*)d_out;

    float *h, *q, *k, *v, *o, *attn;
    cudaGetSymbolAddress((void**)&h,    g_h);
    cudaGetSymbolAddress((void**)&q,    g_q);
    cudaGetSymbolAddress((void**)&k,    g_k);
    cudaGetSymbolAddress((void**)&v,    g_v);
    cudaGetSymbolAddress((void**)&o,    g_o);
    cudaGetSymbolAddress((void**)&attn, g_attn);

    const size_t sCN = (size_t)C_ * NSP;          // 512*4096 per batch
    const size_t sNN = (size_t)NSP * NSP;         // 4096*4096 per batch
    const float scale = 0.044194173824159216f;    // 512^-0.5

    // 1. GroupNorm
    gn_kernel<<<B_ * NGR, 256>>>(x, gamma, beta, h);

    // 2. Q/K/V projections: C[co,p] = W[co,ci] * H[ci,p] + b[co]
    dim3 gproj(NSP / 128, C_ / 128, B_);
    gemm_kernel<false, false, 1><<<gproj, 256>>>(wq, h, q, C_, C_, NSP, NSP,
                                                 0, sCN, sCN, bq, nullptr, 0, 1.f);
    gemm_kernel<false, false, 1><<<gproj, 256>>>(wk, h, k, C_, C_, NSP, NSP,
                                                 0, sCN, sCN, bk, nullptr, 0, 1.f);
    gemm_kernel<false, false, 1><<<gproj, 256>>>(wv, h, v, C_, C_, NSP, NSP,
                                                 0, sCN, sCN, bv, nullptr, 0, 1.f);

    // 3. attn[i,j] = scale * sum_c Q[c,i] K[c,j]   (A transposed: Q is [c][n])
    dim3 gsc(NSP / 128, NSP / 128, B_);
    gemm_kernel<true, false, 2><<<gsc, 256>>>(q, k, attn, C_, NSP, NSP, NSP,
                                              sCN, sCN, sNN, nullptr, nullptr, 0, scale);

    // 4. row softmax (in place)
    softmax_kernel<<<B_ * NSP, 256>>>(attn);

    // 5. o[c,i] = sum_j V[c,j] * P[i,j]    (B transposed: P is [i][j])
    dim3 gpv(NSP / 128, C_ / 128, B_);
    gemm_kernel<false, true, 0><<<gpv, 256>>>(v, attn, o, NSP, NSP, NSP, NSP,
                                              sCN, sNN, sCN, nullptr, nullptr, 0, 1.f);

    // 6. out = x + Wo*o + bo
    gemm_kernel<false, false, 3><<<gproj, 256>>>(wo, o, out, C_, C_, NSP, NSP,
                                                 0, sCN, sCN, bo, x, sCN, 1.f);
}

// round 4
// speedup vs baseline: 1.0010x; 1.0010x over previous
#include <cuda_runtime.h>

// Problem constants
#define B_     2
#define C_     512
#define NSP    4096      // d*h*w = 16*16*16
#define NGR    32        // groups
#define CPG    16        // channels per group

// ---------------------------------------------------------------------------
// Scratch (device globals — no allocation allowed in kernel_launch)
// ---------------------------------------------------------------------------
__device__ float g_h[(size_t)B_ * C_ * NSP];
__device__ float g_q[(size_t)B_ * C_ * NSP];
__device__ float g_k[(size_t)B_ * C_ * NSP];
__device__ float g_v[(size_t)B_ * C_ * NSP];
__device__ float g_o[(size_t)B_ * C_ * NSP];
__device__ float g_attn[(size_t)B_ * NSP * NSP];   // 128 MB

// ---------------------------------------------------------------------------
// f32x2 packed helpers (FFMA2 path — 2x fp32 FMA throughput on sm_103a)
// ---------------------------------------------------------------------------
__device__ __forceinline__ void fma2(unsigned long long& d, unsigned long long a,
                                     unsigned long long b) {
    asm("fma.rn.f32x2 %0, %1, %2, %0;" : "+l"(d) : "l"(a), "l"(b));
}
__device__ __forceinline__ unsigned long long pack2(float x) {
    unsigned long long r;
    asm("mov.b64 %0, {%1, %1};" : "=l"(r) : "f"(x));
    return r;
}
__device__ __forceinline__ void unpack2(unsigned long long v, float& lo, float& hi) {
    asm("mov.b64 {%0, %1}, %2;" : "=f"(lo), "=f"(hi) : "l"(v));
}

// ---------------------------------------------------------------------------
// GroupNorm: one block per (batch, group). 16 channels * 4096 spatial each.
// ---------------------------------------------------------------------------
__global__ __launch_bounds__(256) void gn_kernel(const float* __restrict__ x,
                                                 const float* __restrict__ gamma,
                                                 const float* __restrict__ beta,
                                                 float* __restrict__ h) {
    int b = blockIdx.x >> 5;
    int g = blockIdx.x & 31;
    const size_t base = ((size_t)b * C_ + (size_t)g * CPG) * NSP;
    const float4* xp = (const float4*)(x + base);
    float4* hp = (float4*)(h + base);
    const int M4 = CPG * NSP / 4;   // 16384 float4
    int t = threadIdx.x;

    float s = 0.f, ss = 0.f;
    for (int i = t; i < M4; i += 256) {
        float4 v = xp[i];
        s  += v.x + v.y + v.z + v.w;
        ss += v.x * v.x + v.y * v.y + v.z * v.z + v.w * v.w;
    }
    __shared__ float sm[256], sm2[256];
    sm[t] = s; sm2[t] = ss;
    __syncthreads();
    for (int o = 128; o > 0; o >>= 1) {
        if (t < o) { sm[t] += sm[t + o]; sm2[t] += sm2[t + o]; }
        __syncthreads();
    }
    const float invM = 1.f / (float)(CPG * NSP);
    float mean = sm[0] * invM;
    float var  = sm2[0] * invM - mean * mean;
    float inv  = rsqrtf(var + 1e-6f);

    for (int i = t; i < M4; i += 256) {
        int ch = g * CPG + (i >> 10);        // 1024 float4 per channel
        float gam = gamma[ch] * inv;
        float bet = beta[ch] - mean * gam;
        float4 v = xp[i];
        v.x = v.x * gam + bet; v.y = v.y * gam + bet;
        v.z = v.z * gam + bet; v.w = v.w * gam + bet;
        hp[i] = v;
    }
}

// ---------------------------------------------------------------------------
// Row softmax over 4096 columns. One block (256 thr) per row, data in regs.
// ---------------------------------------------------------------------------
__global__ __launch_bounds__(256) void softmax_kernel(float* __restrict__ attn) {
    float4* p4 = (float4*)(attn + (size_t)blockIdx.x * NSP);
    int t = threadIdx.x;
    float4 v[4];
    float mx = -1e30f;
#pragma unroll
    for (int i = 0; i < 4; i++) {
        v[i] = p4[t + i * 256];
        mx = fmaxf(mx, fmaxf(fmaxf(v[i].x, v[i].y), fmaxf(v[i].z, v[i].w)));
    }
    __shared__ float sm[256];
    sm[t] = mx;
    __syncthreads();
    for (int o = 128; o > 0; o >>= 1) {
        if (t < o) sm[t] = fmaxf(sm[t], sm[t + o]);
        __syncthreads();
    }
    mx = sm[0];
    __syncthreads();

    float s = 0.f;
#pragma unroll
    for (int i = 0; i < 4; i++) {
        v[i].x = __expf(v[i].x - mx); v[i].y = __expf(v[i].y - mx);
        v[i].z = __expf(v[i].z - mx); v[i].w = __expf(v[i].w - mx);
        s += v[i].x + v[i].y + v[i].z + v[i].w;
    }
    sm[t] = s;
    __syncthreads();
    for (int o = 128; o > 0; o >>= 1) {
        if (t < o) sm[t] += sm[t + o];
        __syncthreads();
    }
    float r = 1.f / sm[0];
#pragma unroll
    for (int i = 0; i < 4; i++) {
        v[i].x *= r; v[i].y *= r; v[i].z *= r; v[i].w *= r;
        p4[t + i * 256] = v[i];
    }
}

// ---------------------------------------------------------------------------
// Generic tiled SGEMM, 128x128x16 tile, 256 threads, 8x8 per thread,
// inner loop in packed fma.rn.f32x2 (pairs along N).
//   C[m,n] = (sum_k A_l[m,k] * B_l[k,n]) ; A_l = TA ? A[k][m] : A[m][k]
//   EPI: 0=none, 1=+bias[m], 2=*alpha, 3=+bias[m]+resid[m,n]
// ---------------------------------------------------------------------------
template <bool TA, bool TB, int EPI>
__global__ __launch_bounds__(256) void gemm_kernel(
    const float* __restrict__ A, const float* __restrict__ B, float* __restrict__ Cc,
    int K, int lda, int ldb, int ldc,
    size_t sA, size_t sB, size_t sC,
    const float* __restrict__ bias, const float* __restrict__ resid, size_t sR,
    float alpha) {
    A  += (size_t)blockIdx.z * sA;
    B  += (size_t)blockIdx.z * sB;
    Cc += (size_t)blockIdx.z * sC;
    const float* R = (EPI == 3) ? (resid + (size_t)blockIdx.z * sR) : nullptr;

    __shared__ float As[16][132];
    __shared__ float Bs[16][132];

    int tid = threadIdx.x;
    int n0 = blockIdx.x * 128;
    int m0 = blockIdx.y * 128;
    int tx = tid & 15, ty = tid >> 4;
    int tn0 = tx * 8, tm0 = ty * 8;

    unsigned long long acc[8][4];
#pragma unroll
    for (int i = 0; i < 8; i++)
#pragma unroll
        for (int j = 0; j < 4; j++) acc[i][j] = 0ull;

    for (int k0 = 0; k0 < K; k0 += 16) {
#pragma unroll
        for (int it = 0; it < 2; it++) {
            int f = tid + it * 256;     // 512 float4 per operand tile
            if (!TA) {                   // A[m][k]: [128 x 16] tile, transpose into smem
                int row = f >> 2, kv = (f & 3) * 4;
                float4 v = *(const float4*)(A + (size_t)(m0 + row) * lda + k0 + kv);
                As[kv + 0][row] = v.x; As[kv + 1][row] = v.y;
                As[kv + 2][row] = v.z; As[kv + 3][row] = v.w;
            } else {                     // A[k][m]: [16 x 128] tile, direct
                int kk = f >> 5, mv = (f & 31) * 4;
                float4 v = *(const float4*)(A + (size_t)(k0 + kk) * lda + m0 + mv);
                *(float4*)&As[kk][mv] = v;
            }
            if (!TB) {                   // B[k][n]: [16 x 128] tile, direct
                int kk = f >> 5, nv = (f & 31) * 4;
                float4 v = *(const float4*)(B + (size_t)(k0 + kk) * ldb + n0 + nv);
                *(float4*)&Bs[kk][nv] = v;
            } else {                     // B[n][k]: [128 x 16] tile, transpose into smem
                int row = f >> 2, kv = (f & 3) * 4;
                float4 v = *(const float4*)(B + (size_t)(n0 + row) * ldb + k0 + kv);
                Bs[kv + 0][row] = v.x; Bs[kv + 1][row] = v.y;
                Bs[kv + 2][row] = v.z; Bs[kv + 3][row] = v.w;
            }
        }
        __syncthreads();

#pragma unroll
        for (int kk = 0; kk < 16; kk++) {
            float4 a0 = *(const float4*)&As[kk][tm0];
            float4 a1 = *(const float4*)&As[kk][tm0 + 4];
            const unsigned long long* bp = (const unsigned long long*)&Bs[kk][tn0];
            unsigned long long b2[4] = {bp[0], bp[1], bp[2], bp[3]};
            float av[8] = {a0.x, a0.y, a0.z, a0.w, a1.x, a1.y, a1.z, a1.w};
#pragma unroll
            for (int i = 0; i < 8; i++) {
                unsigned long long ad = pack2(av[i]);
#pragma unroll
                for (int j = 0; j < 4; j++) fma2(acc[i][j], ad, b2[j]);
            }
        }
        __syncthreads();
    }

#pragma unroll
    for (int i = 0; i < 8; i++) {
        int m = m0 + tm0 + i;
        float bv = (EPI == 1 || EPI == 3) ? bias[m] : 0.f;
        float out[8];
#pragma unroll
        for (int j = 0; j < 4; j++) {
            float lo, hi;
            unpack2(acc[i][j], lo, hi);
            if (EPI == 2) { lo *= alpha; hi *= alpha; }
            out[2 * j] = lo + bv;
            out[2 * j + 1] = hi + bv;
        }
        size_t off = (size_t)m * ldc + n0 + tn0;
        if (EPI == 3) {
#pragma unroll
            for (int j = 0; j < 8; j++) out[j] += R[off + j];
        }
        *(float4*)(Cc + off)     = make_float4(out[0], out[1], out[2], out[3]);
        *(float4*)(Cc + off + 4) = make_float4(out[4], out[5], out[6], out[7]);
    }
}

// ---------------------------------------------------------------------------
// Launch
// ---------------------------------------------------------------------------
extern "C" void kernel_launch(void* const* d_in, const int* in_sizes, int n_in,
                              void* d_out, int out_size) {
    (void)in_sizes; (void)n_in; (void)out_size;
    const float* x     = (const float*)d_in[0];
    const float* gamma = (const float*)d_in[1];
    const float* beta  = (const float*)d_in[2];
    const float* wq    = (const float*)d_in[3];
    const float* bq    = (const float*)d_in[4];
    const float* wk    = (const float*)d_in[5];
    const float* bk    = (const float*)d_in[6];
    const float* wv    = (const float*)d_in[7];
    const float* bv    = (const float*)d_in[8];
    const float* wo    = (const float*)d_in[9];
    const float* bo    = (const float*)d_in[10];
    float* out = (float*)d_out;

    float *h, *q, *k, *v, *o, *attn;
    cudaGetSymbolAddress((void**)&h,    g_h);
    cudaGetSymbolAddress((void**)&q,    g_q);
    cudaGetSymbolAddress((void**)&k,    g_k);
    cudaGetSymbolAddress((void**)&v,    g_v);
    cudaGetSymbolAddress((void**)&o,    g_o);
    cudaGetSymbolAddress((void**)&attn, g_attn);

    const size_t sCN = (size_t)C_ * NSP;          // 512*4096 per batch
    const size_t sNN = (size_t)NSP * NSP;         // 4096*4096 per batch
    const float scale = 0.044194173824159216f;    // 512^-0.5

    // 1. GroupNorm
    gn_kernel<<<B_ * NGR, 256>>>(x, gamma, beta, h);

    // 2. Q/K/V projections: C[co,p] = W[co,ci] * H[ci,p] + b[co]
    dim3 gproj(NSP / 128, C_ / 128, B_);
    gemm_kernel<false, false, 1><<<gproj, 256>>>(wq, h, q, C_, C_, NSP, NSP,
                                                 0, sCN, sCN, bq, nullptr, 0, 1.f);
    gemm_kernel<false, false, 1><<<gproj, 256>>>(wk, h, k, C_, C_, NSP, NSP,
                                                 0, sCN, sCN, bk, nullptr, 0, 1.f);
    gemm_kernel<false, false, 1><<<gproj, 256>>>(wv, h, v, C_, C_, NSP, NSP,
                                                 0, sCN, sCN, bv, nullptr, 0, 1.f);

    // 3. attn[i,j] = scale * sum_c Q[c,i] K[c,j]   (A transposed: Q is [c][n])
    dim3 gsc(NSP / 128, NSP / 128, B_);
    gemm_kernel<true, false, 2><<<gsc, 256>>>(q, k, attn, C_, NSP, NSP, NSP,
                                              sCN, sCN, sNN, nullptr, nullptr, 0, scale);

    // 4. row softmax (in place)
    softmax_kernel<<<B_ * NSP, 256>>>(attn);

    // 5. o[c,i] = sum_j V[c,j] * P[i,j]    (B transposed: P is [i][j])
    dim3 gpv(NSP / 128, C_ / 128, B_);
    gemm_kernel<false, true, 0><<<gpv, 256>>>(v, attn, o, NSP, NSP, NSP, NSP,
                                              sCN, sNN, sCN, nullptr, nullptr, 0, 1.f);

    // 6. out = x + Wo*o + bo
    gemm_kernel<false, false, 3><<<gproj, 256>>>(wo, o, out, C_, C_, NSP, NSP,
                                                 0, sCN, sCN, bo, x, sCN, 1.f);
}

// round 7
// speedup vs baseline: 2.1285x; 2.1263x over previous
#include <cuda_runtime.h>
#include <cuda_bf16.h>
#include <cstdint>

#define B_   2
#define C_   512
#define NSP  4096
#define NGR  32
#define CPG  16

// ---- GEMM tile config (mma.sync m16n8k16 bf16) ----
#define BM 128
#define BN 128
#define BK 32
#define SROWB 80                 // padded smem row bytes (32 bf16 = 64B data + 16B pad)
#define TILEB (128 * SROWB)      // 10240 B per operand tile
#define S_AH 0
#define S_AL TILEB
#define S_BH (2 * TILEB)
#define S_BL (3 * TILEB)
#define STG  (4 * TILEB)         // 40960 B per stage
#define SMEMSZ (2 * STG)         // 81920 B total dynamic smem

// ---------------------------------------------------------------------------
// Scratch (device globals)
// ---------------------------------------------------------------------------
__device__ float g_stats[B_ * NGR * 2];
__device__ __align__(16) __nv_bfloat16 g_hT_hi[(size_t)B_ * NSP * C_];
__device__ __align__(16) __nv_bfloat16 g_hT_lo[(size_t)B_ * NSP * C_];
__device__ __align__(16) __nv_bfloat16 g_qT_hi[(size_t)B_ * NSP * C_];
__device__ __align__(16) __nv_bfloat16 g_qT_lo[(size_t)B_ * NSP * C_];
__device__ __align__(16) __nv_bfloat16 g_kT_hi[(size_t)B_ * NSP * C_];
__device__ __align__(16) __nv_bfloat16 g_kT_lo[(size_t)B_ * NSP * C_];
__device__ __align__(16) __nv_bfloat16 g_v_hi[(size_t)B_ * C_ * NSP];
__device__ __align__(16) __nv_bfloat16 g_v_lo[(size_t)B_ * C_ * NSP];
__device__ __align__(16) __nv_bfloat16 g_oT_hi[(size_t)B_ * NSP * C_];
__device__ __align__(16) __nv_bfloat16 g_oT_lo[(size_t)B_ * NSP * C_];
__device__ __align__(16) __nv_bfloat16 g_wq_hi[C_ * C_], g_wq_lo[C_ * C_];
__device__ __align__(16) __nv_bfloat16 g_wk_hi[C_ * C_], g_wk_lo[C_ * C_];
__device__ __align__(16) __nv_bfloat16 g_wv_hi[C_ * C_], g_wv_lo[C_ * C_];
__device__ __align__(16) __nv_bfloat16 g_wo_hi[C_ * C_], g_wo_lo[C_ * C_];
__device__ __align__(16) float g_attn[(size_t)B_ * NSP * NSP];
__device__ __align__(16) __nv_bfloat16 g_P_hi[(size_t)B_ * NSP * NSP];
__device__ __align__(16) __nv_bfloat16 g_P_lo[(size_t)B_ * NSP * NSP];

// ---------------------------------------------------------------------------
// PTX helpers (sm_80+ portable subset only — NO arch-specific 'a' features)
// ---------------------------------------------------------------------------
__device__ __forceinline__ uint32_t smem_u32(const void* p) {
    uint32_t a;
    asm("{ .reg .u64 t; cvta.to.shared.u64 t, %1; cvt.u32.u64 %0, t; }"
        : "=r"(a) : "l"(p));
    return a;
}
__device__ __forceinline__ void cp16(uint32_t dst, const void* src) {
    asm volatile("cp.async.cg.shared.global [%0], [%1], 16;"
                 :: "r"(dst), "l"(src));
}
__device__ __forceinline__ void cp_commit() {
    asm volatile("cp.async.commit_group;" ::: "memory");
}
template <int N> __device__ __forceinline__ void cp_wait() {
    asm volatile("cp.async.wait_group %0;" :: "n"(N) : "memory");
}
__device__ __forceinline__ void ldsm4(uint32_t* r, uint32_t a) {
    asm volatile("ldmatrix.sync.aligned.m8n8.x4.shared.b16 {%0,%1,%2,%3}, [%4];"
                 : "=r"(r[0]), "=r"(r[1]), "=r"(r[2]), "=r"(r[3]) : "r"(a));
}
__device__ __forceinline__ void mma16816(float* d, const uint32_t* a,
                                         uint32_t b0, uint32_t b1) {
    asm volatile(
        "mma.sync.aligned.m16n8k16.row.col.f32.bf16.bf16.f32 "
        "{%0,%1,%2,%3}, {%4,%5,%6,%7}, {%8,%9}, {%0,%1,%2,%3};"
        : "+f"(d[0]), "+f"(d[1]), "+f"(d[2]), "+f"(d[3])
        : "r"(a[0]), "r"(a[1]), "r"(a[2]), "r"(a[3]), "r"(b0), "r"(b1));
}
__device__ __forceinline__ void split2(float v, __nv_bfloat16& h, __nv_bfloat16& l) {
    h = __float2bfloat16(v);
    l = __float2bfloat16(v - __bfloat162float(h));
}

// ---------------------------------------------------------------------------
// GroupNorm stats: one block per (b, g)
// ---------------------------------------------------------------------------
__global__ __launch_bounds__(256) void gn_stats_kernel(const float* __restrict__ x,
                                                       float* __restrict__ stats) {
    int bid = blockIdx.x;
    const float4* xp = (const float4*)(x + (size_t)bid * CPG * NSP);
    const int M4 = CPG * NSP / 4;
    int t = threadIdx.x;
    float s = 0.f, ss = 0.f;
    for (int i = t; i < M4; i += 256) {
        float4 v = xp[i];
        s += v.x + v.y + v.z + v.w;
        ss += v.x * v.x + v.y * v.y + v.z * v.z + v.w * v.w;
    }
    __shared__ float sm[256], sm2[256];
    sm[t] = s; sm2[t] = ss;
    __syncthreads();
    for (int o = 128; o > 0; o >>= 1) {
        if (t < o) { sm[t] += sm[t + o]; sm2[t] += sm2[t + o]; }
        __syncthreads();
    }
    if (t == 0) {
        const float invM = 1.f / (float)(CPG * NSP);
        float mean = sm[0] * invM;
        float var = sm2[0] * invM - mean * mean;
        stats[bid * 2] = mean;
        stats[bid * 2 + 1] = rsqrtf(var + 1e-6f);
    }
}

// ---------------------------------------------------------------------------
// Apply GN + transpose + bf16-split: x[c][p] -> hT[p][c] (hi/lo)
// block (32,8), grid (NSP/32, C_/32, B_)
// ---------------------------------------------------------------------------
__global__ void gn_apply_t_kernel(const float* __restrict__ x,
                                  const float* __restrict__ gamma,
                                  const float* __restrict__ beta,
                                  const float* __restrict__ stats,
                                  __nv_bfloat16* __restrict__ hT_hi,
                                  __nv_bfloat16* __restrict__ hT_lo) {
    __shared__ float sm[32][33];
    int p0 = blockIdx.x * 32, c0 = blockIdx.y * 32, b = blockIdx.z;
    int tx = threadIdx.x, ty = threadIdx.y;
    const float* xb = x + ((size_t)b * C_ + c0) * NSP;
#pragma unroll
    for (int r = 0; r < 4; ++r) {
        int c = ty * 4 + r;
        sm[c][tx] = xb[(size_t)c * NSP + p0 + tx];
    }
    __syncthreads();
    int cg = c0 + tx;
    int g = cg >> 4;
    float mean = stats[(b * NGR + g) * 2];
    float inv  = stats[(b * NGR + g) * 2 + 1];
    float sc = gamma[cg] * inv;
    float sh = beta[cg] - mean * sc;
#pragma unroll
    for (int r = 0; r < 4; ++r) {
        int pl = ty * 4 + r;
        float v = sm[tx][pl] * sc + sh;
        __nv_bfloat16 h, l;
        split2(v, h, l);
        size_t o = ((size_t)b * NSP + p0 + pl) * C_ + cg;
        hT_hi[o] = h;
        hT_lo[o] = l;
    }
}

// ---------------------------------------------------------------------------
// Weight bf16-split
// ---------------------------------------------------------------------------
__global__ __launch_bounds__(256) void split_kernel(const float* __restrict__ s,
                                                    __nv_bfloat16* __restrict__ hi,
                                                    __nv_bfloat16* __restrict__ lo,
                                                    int n4) {
    int i = blockIdx.x * 256 + threadIdx.x;
    if (i >= n4) return;
    float4 v = ((const float4*)s)[i];
    __nv_bfloat16 hx, lx, hy, ly, hz, lz, hw, lw;
    split2(v.x, hx, lx); split2(v.y, hy, ly);
    split2(v.z, hz, lz); split2(v.w, hw, lw);
    ((__nv_bfloat162*)hi)[2 * i]     = __nv_bfloat162(hx, hy);
    ((__nv_bfloat162*)hi)[2 * i + 1] = __nv_bfloat162(hz, hw);
    ((__nv_bfloat162*)lo)[2 * i]     = __nv_bfloat162(lx, ly);
    ((__nv_bfloat162*)lo)[2 * i + 1] = __nv_bfloat162(lz, lw);
}

// ---------------------------------------------------------------------------
// Row softmax (4096 cols) -> bf16 hi/lo split of P
// ---------------------------------------------------------------------------
__global__ __launch_bounds__(256) void softmax_kernel(const float* __restrict__ attn,
                                                      __nv_bfloat16* __restrict__ Ph,
                                                      __nv_bfloat16* __restrict__ Pl) {
    const float4* p4 = (const float4*)(attn + (size_t)blockIdx.x * NSP);
    int t = threadIdx.x;
    float4 v[4];
    float mx = -1e30f;
#pragma unroll
    for (int i = 0; i < 4; i++) {
        v[i] = p4[t + i * 256];
        mx = fmaxf(mx, fmaxf(fmaxf(v[i].x, v[i].y), fmaxf(v[i].z, v[i].w)));
    }
    __shared__ float sm[256];
    sm[t] = mx;
    __syncthreads();
    for (int o = 128; o > 0; o >>= 1) {
        if (t < o) sm[t] = fmaxf(sm[t], sm[t + o]);
        __syncthreads();
    }
    mx = sm[0];
    __syncthreads();
    float s = 0.f;
#pragma unroll
    for (int i = 0; i < 4; i++) {
        v[i].x = __expf(v[i].x - mx); v[i].y = __expf(v[i].y - mx);
        v[i].z = __expf(v[i].z - mx); v[i].w = __expf(v[i].w - mx);
        s += v[i].x + v[i].y + v[i].z + v[i].w;
    }
    sm[t] = s;
    __syncthreads();
    for (int o = 128; o > 0; o >>= 1) {
        if (t < o) sm[t] += sm[t + o];
        __syncthreads();
    }
    float r = 1.f / sm[0];
    __nv_bfloat162* ph2 = (__nv_bfloat162*)(Ph + (size_t)blockIdx.x * NSP);
    __nv_bfloat162* pl2 = (__nv_bfloat162*)(Pl + (size_t)blockIdx.x * NSP);
#pragma unroll
    for (int i = 0; i < 4; i++) {
        int f = t + i * 256;
        float a = v[i].x * r, b = v[i].y * r, c = v[i].z * r, d = v[i].w * r;
        __nv_bfloat16 ha, la, hb, lb, hc, lc, hd, ld_;
        split2(a, ha, la); split2(b, hb, lb); split2(c, hc, lc); split2(d, hd, ld_);
        ph2[2 * f]     = __nv_bfloat162(ha, hb);
        ph2[2 * f + 1] = __nv_bfloat162(hc, hd);
        pl2[2 * f]     = __nv_bfloat162(la, lb);
        pl2[2 * f + 1] = __nv_bfloat162(lc, ld_);
    }
}

// ---------------------------------------------------------------------------
// mma.sync split-bf16 GEMM: C[m,n] = sum_k A[m,k]*B[n,k] (both K-major).
// 128x128x32 tile, 256 threads = 8 warps (4x2), warp tile 32x64,
// cp.async 2-stage pipeline, ldmatrix fragment loads.
// EPI: 0=bf16 out          1=bf16 out + bias[n]
//      2=bf16 out + bias[m] 3=f32 out * alpha
//      4=f32 out + bias[m] + resid
// ---------------------------------------------------------------------------
template <int EPI>
__global__ __launch_bounds__(256) void gemm5(
    const __nv_bfloat16* __restrict__ Ah, const __nv_bfloat16* __restrict__ Al,
    const __nv_bfloat16* __restrict__ Bh, const __nv_bfloat16* __restrict__ Bl,
    int lda, int ldb, int K, size_t sA, size_t sB,
    void* __restrict__ C1, void* __restrict__ C2, int ldc, size_t sC,
    const float* __restrict__ bias, const float* __restrict__ resid, size_t sR,
    float alpha) {
    extern __shared__ char dsm[];
    uint32_t sb = smem_u32(dsm);
    int tid = threadIdx.x, wid = tid >> 5, lane = tid & 31;
    int n0 = blockIdx.x * BN, m0 = blockIdx.y * BM, bz = blockIdx.z;
    Ah += bz * sA; Al += bz * sA; Bh += bz * sB; Bl += bz * sB;

    int wm = wid & 3;        // warp m index (4)  -> m offset wm*32
    int wn = wid >> 2;       // warp n index (2)  -> n offset wn*64

    // ldmatrix lane address decode
    int g = lane >> 3, rr = lane & 7;
    int aRow = ((g & 1) << 3) + rr;   // within m16 frag
    int aK   = (g >> 1) << 3;         // k half
    int bRow = ((g >> 1) << 3) + rr;  // within n16 (2 n-frags)
    int bK   = (g & 1) << 3;

    float acc[2][8][4];
#pragma unroll
    for (int mf = 0; mf < 2; ++mf)
#pragma unroll
        for (int nf = 0; nf < 8; ++nf)
#pragma unroll
            for (int j = 0; j < 4; ++j) acc[mf][nf][j] = 0.f;

    // fill lane decode: 512 16B-chunks per operand tile, 2 per thread
    int frow0 = tid >> 2, fkc = (tid & 3) << 3;   // kc in bf16 elems

    const int nk = K / BK;
    // prologue: stage 0
    {
        uint32_t sd = sb;
#pragma unroll
        for (int p = 0; p < 2; ++p) {
            int row = frow0 + p * 64;
            uint32_t off = (uint32_t)(row * SROWB + (fkc << 1));
            size_t ga = (size_t)(m0 + row) * lda + fkc;
            size_t gb = (size_t)(n0 + row) * ldb + fkc;
            cp16(sd + S_AH + off, Ah + ga);
            cp16(sd + S_AL + off, Al + ga);
            cp16(sd + S_BH + off, Bh + gb);
            cp16(sd + S_BL + off, Bl + gb);
        }
        cp_commit();
    }

    for (int c = 0; c < nk; ++c) {
        if (c + 1 < nk) {
            uint32_t sd = sb + ((c + 1) & 1) * STG;
            int k0 = (c + 1) * BK;
#pragma unroll
            for (int p = 0; p < 2; ++p) {
                int row = frow0 + p * 64;
                uint32_t off = (uint32_t)(row * SROWB + (fkc << 1));
                size_t ga = (size_t)(m0 + row) * lda + k0 + fkc;
                size_t gb = (size_t)(n0 + row) * ldb + k0 + fkc;
                cp16(sd + S_AH + off, Ah + ga);
                cp16(sd + S_AL + off, Al + ga);
                cp16(sd + S_BH + off, Bh + gb);
                cp16(sd + S_BL + off, Bl + gb);
            }
            cp_commit();
            cp_wait<1>();
        } else {
            cp_wait<0>();
        }
        __syncthreads();

        uint32_t sbs = sb + (c & 1) * STG;
#pragma unroll
        for (int kk = 0; kk < BK; kk += 16) {
            uint32_t ah[2][4], al[2][4];
#pragma unroll
            for (int mf = 0; mf < 2; ++mf) {
                uint32_t ro = (uint32_t)((wm * 32 + mf * 16 + aRow) * SROWB +
                                         (kk + aK) * 2);
                ldsm4(ah[mf], sbs + S_AH + ro);
                ldsm4(al[mf], sbs + S_AL + ro);
            }
            uint32_t bh[4][4], bl[4][4];
#pragma unroll
            for (int nf2 = 0; nf2 < 4; ++nf2) {
                uint32_t ro = (uint32_t)((wn * 64 + nf2 * 16 + bRow) * SROWB +
                                         (kk + bK) * 2);
                ldsm4(bh[nf2], sbs + S_BH + ro);
                ldsm4(bl[nf2], sbs + S_BL + ro);
            }
#pragma unroll
            for (int mf = 0; mf < 2; ++mf)
#pragma unroll
                for (int nf = 0; nf < 8; ++nf) {
                    const uint32_t* bhp = &bh[nf >> 1][(nf & 1) * 2];
                    const uint32_t* blp = &bl[nf >> 1][(nf & 1) * 2];
                    float* d = acc[mf][nf];
                    mma16816(d, ah[mf], bhp[0], bhp[1]);   // Ah*Bh
                    mma16816(d, al[mf], bhp[0], bhp[1]);   // Al*Bh
                    mma16816(d, ah[mf], blp[0], blp[1]);   // Ah*Bl
                }
        }
        __syncthreads();
    }

    // epilogue: write accumulators
    int qrow = lane >> 2;
    int qcol = (lane & 3) * 2;
#pragma unroll
    for (int mf = 0; mf < 2; ++mf)
#pragma unroll
        for (int nf = 0; nf < 8; ++nf)
#pragma unroll
            for (int half = 0; half < 2; ++half) {
                int m = m0 + wm * 32 + mf * 16 + qrow + half * 8;
                int n = n0 + wn * 64 + nf * 8 + qcol;
                float v0 = acc[mf][nf][half * 2 + 0];
                float v1 = acc[mf][nf][half * 2 + 1];
                size_t off = (size_t)m * ldc + n;
                if (EPI <= 2) {
                    float b0 = 0.f, b1 = 0.f;
                    if (EPI == 1) { b0 = bias[n]; b1 = bias[n + 1]; }
                    if (EPI == 2) { b0 = bias[m]; b1 = bias[m]; }
                    __nv_bfloat16 h0, l0, h1, l1;
                    split2(v0 + b0, h0, l0);
                    split2(v1 + b1, h1, l1);
                    *(__nv_bfloat162*)((__nv_bfloat16*)C1 + bz * sC + off) =
                        __nv_bfloat162(h0, h1);
                    *(__nv_bfloat162*)((__nv_bfloat16*)C2 + bz * sC + off) =
                        __nv_bfloat162(l0, l1);
                } else if (EPI == 3) {
                    *(float2*)((float*)C1 + bz * sC + off) =
                        make_float2(v0 * alpha, v1 * alpha);
                } else {
                    float bm = bias[m];
                    const float* R = resid + bz * sR + off;
                    *(float2*)((float*)C1 + bz * sC + off) =
                        make_float2(v0 + bm + R[0], v1 + bm + R[1]);
                }
            }
}

// ---------------------------------------------------------------------------
// Launch
// ---------------------------------------------------------------------------
extern "C" void kernel_launch(void* const* d_in, const int* in_sizes, int n_in,
                              void* d_out, int out_size) {
    (void)in_sizes; (void)n_in; (void)out_size;
    const float* x     = (const float*)d_in[0];
    const float* gamma = (const float*)d_in[1];
    const float* beta  = (const float*)d_in[2];
    const float* wq    = (const float*)d_in[3];
    const float* bq    = (const float*)d_in[4];
    const float* wk    = (const float*)d_in[5];
    const float* bk    = (const float*)d_in[6];
    const float* wv    = (const float*)d_in[7];
    const float* bv    = (const float*)d_in[8];
    const float* wo    = (const float*)d_in[9];
    const float* bo    = (const float*)d_in[10];
    float* out = (float*)d_out;

    float *stats, *attn;
    __nv_bfloat16 *hTh, *hTl, *qTh, *qTl, *kTh, *kTl, *vh, *vl, *oTh, *oTl;
    __nv_bfloat16 *wqh, *wql, *wkh, *wkl, *wvh, *wvl, *woh, *wol, *Ph, *Pl;
    cudaGetSymbolAddress((void**)&stats, g_stats);
    cudaGetSymbolAddress((void**)&attn,  g_attn);
    cudaGetSymbolAddress((void**)&hTh, g_hT_hi); cudaGetSymbolAddress((void**)&hTl, g_hT_lo);
    cudaGetSymbolAddress((void**)&qTh, g_qT_hi); cudaGetSymbolAddress((void**)&qTl, g_qT_lo);
    cudaGetSymbolAddress((void**)&kTh, g_kT_hi); cudaGetSymbolAddress((void**)&kTl, g_kT_lo);
    cudaGetSymbolAddress((void**)&vh,  g_v_hi);  cudaGetSymbolAddress((void**)&vl,  g_v_lo);
    cudaGetSymbolAddress((void**)&oTh, g_oT_hi); cudaGetSymbolAddress((void**)&oTl, g_oT_lo);
    cudaGetSymbolAddress((void**)&wqh, g_wq_hi); cudaGetSymbolAddress((void**)&wql, g_wq_lo);
    cudaGetSymbolAddress((void**)&wkh, g_wk_hi); cudaGetSymbolAddress((void**)&wkl, g_wk_lo);
    cudaGetSymbolAddress((void**)&wvh, g_wv_hi); cudaGetSymbolAddress((void**)&wvl, g_wv_lo);
    cudaGetSymbolAddress((void**)&woh, g_wo_hi); cudaGetSymbolAddress((void**)&wol, g_wo_lo);
    cudaGetSymbolAddress((void**)&Ph,  g_P_hi);  cudaGetSymbolAddress((void**)&Pl,  g_P_lo);

    cudaFuncSetAttribute(gemm5<0>, cudaFuncAttributeMaxDynamicSharedMemorySize, SMEMSZ);
    cudaFuncSetAttribute(gemm5<1>, cudaFuncAttributeMaxDynamicSharedMemorySize, SMEMSZ);
    cudaFuncSetAttribute(gemm5<2>, cudaFuncAttributeMaxDynamicSharedMemorySize, SMEMSZ);
    cudaFuncSetAttribute(gemm5<3>, cudaFuncAttributeMaxDynamicSharedMemorySize, SMEMSZ);
    cudaFuncSetAttribute(gemm5<4>, cudaFuncAttributeMaxDynamicSharedMemorySize, SMEMSZ);

    const size_t sCN = (size_t)C_ * NSP;
    const size_t sNN = (size_t)NSP * NSP;
    const float scale = 0.044194173824159216f;   // 512^-0.5

    // 1. GroupNorm (stats, then apply+transpose+split -> hT[p][c])
    gn_stats_kernel<<<B_ * NGR, 256>>>(x, stats);
    gn_apply_t_kernel<<<dim3(NSP / 32, C_ / 32, B_), dim3(32, 8)>>>(
        x, gamma, beta, stats, hTh, hTl);

    // 2. weight splits
    split_kernel<<<C_ * C_ / 1024, 256>>>(wq, wqh, wql, C_ * C_ / 4);
    split_kernel<<<C_ * C_ / 1024, 256>>>(wk, wkh, wkl, C_ * C_ / 4);
    split_kernel<<<C_ * C_ / 1024, 256>>>(wv, wvh, wvl, C_ * C_ / 4);
    split_kernel<<<C_ * C_ / 1024, 256>>>(wo, woh, wol, C_ * C_ / 4);

    // 3. qT[p][co] = hT[p][:] . Wq[co][:]  (M=4096,N=512,K=512), +bias[n]
    dim3 gQ(C_ / BN, NSP / BM, B_);
    gemm5<1><<<gQ, 256, SMEMSZ>>>(hTh, hTl, wqh, wql, C_, C_, C_, sCN, 0,
                                  qTh, qTl, C_, sCN, bq, nullptr, 0, 1.f);
    gemm5<1><<<gQ, 256, SMEMSZ>>>(hTh, hTl, wkh, wkl, C_, C_, C_, sCN, 0,
                                  kTh, kTl, C_, sCN, bk, nullptr, 0, 1.f);
    // v[co][p] = Wv[co][:] . hT[p][:]  (M=512,N=4096,K=512), +bias[m]
    dim3 gV(NSP / BN, C_ / BM, B_);
    gemm5<2><<<gV, 256, SMEMSZ>>>(wvh, wvl, hTh, hTl, C_, C_, C_, 0, sCN,
                                  vh, vl, NSP, sCN, bv, nullptr, 0, 1.f);

    // 4. attn[i][j] = scale * qT[i][:] . kT[j][:]  (M=N=4096,K=512) f32
    dim3 gS(NSP / BN, NSP / BM, B_);
    gemm5<3><<<gS, 256, SMEMSZ>>>(qTh, qTl, kTh, kTl, C_, C_, C_, sCN, sCN,
                                  attn, nullptr, NSP, sNN, nullptr, nullptr, 0, scale);

    // 5. softmax -> P hi/lo
    softmax_kernel<<<B_ * NSP, 256>>>(attn, Ph, Pl);

    // 6. oT[i][c] = P[i][:] . v[c][:]  (M=4096,N=512,K=4096) bf16
    dim3 gO(C_ / BN, NSP / BM, B_);
    gemm5<0><<<gO, 256, SMEMSZ>>>(Ph, Pl, vh, vl, NSP, NSP, NSP, sNN, sCN,
                                  oTh, oTl, C_, sCN, nullptr, nullptr, 0, 1.f);

    // 7. out[c][p] = x + bo[c] + Wo[c][:] . oT[p][:]  (M=512,N=4096,K=512) f32
    dim3 gF(NSP / BN, C_ / BM, B_);
    gemm5<4><<<gF, 256, SMEMSZ>>>(woh, wol, oTh, oTl, C_, C_, C_, 0, sCN,
                                  out, nullptr, NSP, sCN, bo, x, sCN, 1.f);
}

// round 8
// speedup vs baseline: 2.9824x; 1.4012x over previous
#include <cuda_runtime.h>
#include <cuda_bf16.h>
#include <cstdint>

#define B_   2
#define C_   512
#define NSP  4096
#define NGR  32
#define CPG  16

// ---- GEMM tile config (mma.sync m16n8k16 bf16) ----
#define BM 128
#define BN 128
#define BK 32
#define SROWB 80                 // padded smem row bytes (32 bf16 = 64B data + 16B pad)
#define TILEB (128 * SROWB)      // 10240 B per operand tile
#define S_AH 0
#define S_AL TILEB
#define S_BH (2 * TILEB)
#define S_BL (3 * TILEB)
#define STG  (4 * TILEB)         // 40960 B per stage
#define SMEMSZ (2 * STG)         // 81920 B total dynamic smem

// ---------------------------------------------------------------------------
// Scratch (device globals)
// ---------------------------------------------------------------------------
__device__ float g_stats[B_ * NGR * 2];
__device__ __align__(16) __nv_bfloat16 g_hT_hi[(size_t)B_ * NSP * C_];
__device__ __align__(16) __nv_bfloat16 g_hT_lo[(size_t)B_ * NSP * C_];
__device__ __align__(16) __nv_bfloat16 g_qT_hi[(size_t)B_ * NSP * C_];
__device__ __align__(16) __nv_bfloat16 g_qT_lo[(size_t)B_ * NSP * C_];
__device__ __align__(16) __nv_bfloat16 g_kT_hi[(size_t)B_ * NSP * C_];
__device__ __align__(16) __nv_bfloat16 g_kT_lo[(size_t)B_ * NSP * C_];
__device__ __align__(16) __nv_bfloat16 g_v_hi[(size_t)B_ * C_ * NSP];
__device__ __align__(16) __nv_bfloat16 g_v_lo[(size_t)B_ * C_ * NSP];
__device__ __align__(16) __nv_bfloat16 g_oT_hi[(size_t)B_ * NSP * C_];
__device__ __align__(16) __nv_bfloat16 g_oT_lo[(size_t)B_ * NSP * C_];
__device__ __align__(16) __nv_bfloat16 g_wq_hi[C_ * C_], g_wq_lo[C_ * C_];
__device__ __align__(16) __nv_bfloat16 g_wk_hi[C_ * C_], g_wk_lo[C_ * C_];
__device__ __align__(16) __nv_bfloat16 g_wv_hi[C_ * C_], g_wv_lo[C_ * C_];
__device__ __align__(16) __nv_bfloat16 g_wo_hi[C_ * C_], g_wo_lo[C_ * C_];
__device__ __align__(16) float g_attn[(size_t)B_ * NSP * NSP];
__device__ __align__(16) __nv_bfloat16 g_P_hi[(size_t)B_ * NSP * NSP];

// ---------------------------------------------------------------------------
// PTX helpers (sm_80+ portable subset only — NO arch-specific 'a' features)
// ---------------------------------------------------------------------------
__device__ __forceinline__ uint32_t smem_u32(const void* p) {
    uint32_t a;
    asm("{ .reg .u64 t; cvta.to.shared.u64 t, %1; cvt.u32.u64 %0, t; }"
        : "=r"(a) : "l"(p));
    return a;
}
__device__ __forceinline__ void cp16(uint32_t dst, const void* src) {
    asm volatile("cp.async.cg.shared.global [%0], [%1], 16;"
                 :: "r"(dst), "l"(src));
}
__device__ __forceinline__ void cp_commit() {
    asm volatile("cp.async.commit_group;" ::: "memory");
}
template <int N> __device__ __forceinline__ void cp_wait() {
    asm volatile("cp.async.wait_group %0;" :: "n"(N) : "memory");
}
__device__ __forceinline__ void ldsm4(uint32_t* r, uint32_t a) {
    asm volatile("ldmatrix.sync.aligned.m8n8.x4.shared.b16 {%0,%1,%2,%3}, [%4];"
                 : "=r"(r[0]), "=r"(r[1]), "=r"(r[2]), "=r"(r[3]) : "r"(a));
}
__device__ __forceinline__ void mma16816(float* d, const uint32_t* a,
                                         uint32_t b0, uint32_t b1) {
    asm volatile(
        "mma.sync.aligned.m16n8k16.row.col.f32.bf16.bf16.f32 "
        "{%0,%1,%2,%3}, {%4,%5,%6,%7}, {%8,%9}, {%0,%1,%2,%3};"
        : "+f"(d[0]), "+f"(d[1]), "+f"(d[2]), "+f"(d[3])
        : "r"(a[0]), "r"(a[1]), "r"(a[2]), "r"(a[3]), "r"(b0), "r"(b1));
}
__device__ __forceinline__ void split2(float v, __nv_bfloat16& h, __nv_bfloat16& l) {
    h = __float2bfloat16(v);
    l = __float2bfloat16(v - __bfloat162float(h));
}

// ---------------------------------------------------------------------------
// GroupNorm stats: one block per (b, g)
// ---------------------------------------------------------------------------
__global__ __launch_bounds__(256) void gn_stats_kernel(const float* __restrict__ x,
                                                       float* __restrict__ stats) {
    int bid = blockIdx.x;
    const float4* xp = (const float4*)(x + (size_t)bid * CPG * NSP);
    const int M4 = CPG * NSP / 4;
    int t = threadIdx.x;
    float s = 0.f, ss = 0.f;
    for (int i = t; i < M4; i += 256) {
        float4 v = xp[i];
        s += v.x + v.y + v.z + v.w;
        ss += v.x * v.x + v.y * v.y + v.z * v.z + v.w * v.w;
    }
    __shared__ float sm[256], sm2[256];
    sm[t] = s; sm2[t] = ss;
    __syncthreads();
    for (int o = 128; o > 0; o >>= 1) {
        if (t < o) { sm[t] += sm[t + o]; sm2[t] += sm2[t + o]; }
        __syncthreads();
    }
    if (t == 0) {
        const float invM = 1.f / (float)(CPG * NSP);
        float mean = sm[0] * invM;
        float var = sm2[0] * invM - mean * mean;
        stats[bid * 2] = mean;
        stats[bid * 2 + 1] = rsqrtf(var + 1e-6f);
    }
}

// ---------------------------------------------------------------------------
// Apply GN + transpose + bf16-split: x[c][p] -> hT[p][c] (hi/lo)
// ---------------------------------------------------------------------------
__global__ void gn_apply_t_kernel(const float* __restrict__ x,
                                  const float* __restrict__ gamma,
                                  const float* __restrict__ beta,
                                  const float* __restrict__ stats,
                                  __nv_bfloat16* __restrict__ hT_hi,
                                  __nv_bfloat16* __restrict__ hT_lo) {
    __shared__ float sm[32][33];
    int p0 = blockIdx.x * 32, c0 = blockIdx.y * 32, b = blockIdx.z;
    int tx = threadIdx.x, ty = threadIdx.y;
    const float* xb = x + ((size_t)b * C_ + c0) * NSP;
#pragma unroll
    for (int r = 0; r < 4; ++r) {
        int c = ty * 4 + r;
        sm[c][tx] = xb[(size_t)c * NSP + p0 + tx];
    }
    __syncthreads();
    int cg = c0 + tx;
    int g = cg >> 4;
    float mean = stats[(b * NGR + g) * 2];
    float inv  = stats[(b * NGR + g) * 2 + 1];
    float sc = gamma[cg] * inv;
    float sh = beta[cg] - mean * sc;
#pragma unroll
    for (int r = 0; r < 4; ++r) {
        int pl = ty * 4 + r;
        float v = sm[tx][pl] * sc + sh;
        __nv_bfloat16 h, l;
        split2(v, h, l);
        size_t o = ((size_t)b * NSP + p0 + pl) * C_ + cg;
        hT_hi[o] = h;
        hT_lo[o] = l;
    }
}

// ---------------------------------------------------------------------------
// Weight bf16-split
// ---------------------------------------------------------------------------
__global__ __launch_bounds__(256) void split_kernel(const float* __restrict__ s,
                                                    __nv_bfloat16* __restrict__ hi,
                                                    __nv_bfloat16* __restrict__ lo,
                                                    int n4) {
    int i = blockIdx.x * 256 + threadIdx.x;
    if (i >= n4) return;
    float4 v = ((const float4*)s)[i];
    __nv_bfloat16 hx, lx, hy, ly, hz, lz, hw, lw;
    split2(v.x, hx, lx); split2(v.y, hy, ly);
    split2(v.z, hz, lz); split2(v.w, hw, lw);
    ((__nv_bfloat162*)hi)[2 * i]     = __nv_bfloat162(hx, hy);
    ((__nv_bfloat162*)hi)[2 * i + 1] = __nv_bfloat162(hz, hw);
    ((__nv_bfloat162*)lo)[2 * i]     = __nv_bfloat162(lx, ly);
    ((__nv_bfloat162*)lo)[2 * i + 1] = __nv_bfloat162(lz, lw);
}

// ---------------------------------------------------------------------------
// Row softmax (4096 cols) -> bf16 P (hi only; lo term dropped by 2-term PV)
// ---------------------------------------------------------------------------
__global__ __launch_bounds__(256) void softmax_kernel(const float* __restrict__ attn,
                                                      __nv_bfloat16* __restrict__ Ph) {
    const float4* p4 = (const float4*)(attn + (size_t)blockIdx.x * NSP);
    int t = threadIdx.x;
    float4 v[4];
    float mx = -1e30f;
#pragma unroll
    for (int i = 0; i < 4; i++) {
        v[i] = p4[t + i * 256];
        mx = fmaxf(mx, fmaxf(fmaxf(v[i].x, v[i].y), fmaxf(v[i].z, v[i].w)));
    }
    __shared__ float sm[256];
    sm[t] = mx;
    __syncthreads();
    for (int o = 128; o > 0; o >>= 1) {
        if (t < o) sm[t] = fmaxf(sm[t], sm[t + o]);
        __syncthreads();
    }
    mx = sm[0];
    __syncthreads();
    float s = 0.f;
#pragma unroll
    for (int i = 0; i < 4; i++) {
        v[i].x = __expf(v[i].x - mx); v[i].y = __expf(v[i].y - mx);
        v[i].z = __expf(v[i].z - mx); v[i].w = __expf(v[i].w - mx);
        s += v[i].x + v[i].y + v[i].z + v[i].w;
    }
    sm[t] = s;
    __syncthreads();
    for (int o = 128; o > 0; o >>= 1) {
        if (t < o) sm[t] += sm[t + o];
        __syncthreads();
    }
    float r = 1.f / sm[0];
    __nv_bfloat162* ph2 = (__nv_bfloat162*)(Ph + (size_t)blockIdx.x * NSP);
#pragma unroll
    for (int i = 0; i < 4; i++) {
        int f = t + i * 256;
        ph2[2 * f]     = __nv_bfloat162(__float2bfloat16(v[i].x * r),
                                        __float2bfloat16(v[i].y * r));
        ph2[2 * f + 1] = __nv_bfloat162(__float2bfloat16(v[i].z * r),
                                        __float2bfloat16(v[i].w * r));
    }
}

// ---------------------------------------------------------------------------
// mma.sync split-bf16 GEMM: C[m,n] = sum_k A[m,k]*B[n,k] (both K-major).
// 128x128x32 tile, 8 warps (4x2), warp tile 32x64, cp.async 2-stage pipeline.
// TERMS=3: Ah*Bh + Al*Bh + Ah*Bl   TERMS=2: Ah*Bh + Ah*Bl (Al unused/null)
// EPI: 0=bf16 out          1=bf16 out + bias[n]
//      2=bf16 out + bias[m] 3=f32 out * alpha
//      4=f32 out + bias[m] + resid
// ---------------------------------------------------------------------------
template <int EPI, int TERMS>
__global__ __launch_bounds__(256) void gemm5(
    const __nv_bfloat16* __restrict__ Ah, const __nv_bfloat16* __restrict__ Al,
    const __nv_bfloat16* __restrict__ Bh, const __nv_bfloat16* __restrict__ Bl,
    int lda, int ldb, int K, size_t sA, size_t sB,
    void* __restrict__ C1, void* __restrict__ C2, int ldc, size_t sC,
    const float* __restrict__ bias, const float* __restrict__ resid, size_t sR,
    float alpha) {
    extern __shared__ char dsm[];
    uint32_t sb = smem_u32(dsm);
    int tid = threadIdx.x, wid = tid >> 5, lane = tid & 31;
    int n0 = blockIdx.x * BN, m0 = blockIdx.y * BM, bz = blockIdx.z;
    Ah += bz * sA;
    if (TERMS == 3) Al += bz * sA;
    Bh += bz * sB; Bl += bz * sB;

    int wm = wid & 3;
    int wn = wid >> 2;

    int g = lane >> 3, rr = lane & 7;
    int aRow = ((g & 1) << 3) + rr;
    int aK   = (g >> 1) << 3;
    int bRow = ((g >> 1) << 3) + rr;
    int bK   = (g & 1) << 3;

    float acc[2][8][4];
#pragma unroll
    for (int mf = 0; mf < 2; ++mf)
#pragma unroll
        for (int nf = 0; nf < 8; ++nf)
#pragma unroll
            for (int j = 0; j < 4; ++j) acc[mf][nf][j] = 0.f;

    int frow0 = tid >> 2, fkc = (tid & 3) << 3;

    const int nk = K / BK;
    {
        uint32_t sd = sb;
#pragma unroll
        for (int p = 0; p < 2; ++p) {
            int row = frow0 + p * 64;
            uint32_t off = (uint32_t)(row * SROWB + (fkc << 1));
            size_t ga = (size_t)(m0 + row) * lda + fkc;
            size_t gb = (size_t)(n0 + row) * ldb + fkc;
            cp16(sd + S_AH + off, Ah + ga);
            if (TERMS == 3) cp16(sd + S_AL + off, Al + ga);
            cp16(sd + S_BH + off, Bh + gb);
            cp16(sd + S_BL + off, Bl + gb);
        }
        cp_commit();
    }

    for (int c = 0; c < nk; ++c) {
        if (c + 1 < nk) {
            uint32_t sd = sb + ((c + 1) & 1) * STG;
            int k0 = (c + 1) * BK;
#pragma unroll
            for (int p = 0; p < 2; ++p) {
                int row = frow0 + p * 64;
                uint32_t off = (uint32_t)(row * SROWB + (fkc << 1));
                size_t ga = (size_t)(m0 + row) * lda + k0 + fkc;
                size_t gb = (size_t)(n0 + row) * ldb + k0 + fkc;
                cp16(sd + S_AH + off, Ah + ga);
                if (TERMS == 3) cp16(sd + S_AL + off, Al + ga);
                cp16(sd + S_BH + off, Bh + gb);
                cp16(sd + S_BL + off, Bl + gb);
            }
            cp_commit();
            cp_wait<1>();
        } else {
            cp_wait<0>();
        }
        __syncthreads();

        uint32_t sbs = sb + (c & 1) * STG;
#pragma unroll
        for (int kk = 0; kk < BK; kk += 16) {
            uint32_t ah[2][4], al[2][4];
#pragma unroll
            for (int mf = 0; mf < 2; ++mf) {
                uint32_t ro = (uint32_t)((wm * 32 + mf * 16 + aRow) * SROWB +
                                         (kk + aK) * 2);
                ldsm4(ah[mf], sbs + S_AH + ro);
                if (TERMS == 3) ldsm4(al[mf], sbs + S_AL + ro);
            }
            uint32_t bh[4][4], bl[4][4];
#pragma unroll
            for (int nf2 = 0; nf2 < 4; ++nf2) {
                uint32_t ro = (uint32_t)((wn * 64 + nf2 * 16 + bRow) * SROWB +
                                         (kk + bK) * 2);
                ldsm4(bh[nf2], sbs + S_BH + ro);
                ldsm4(bl[nf2], sbs + S_BL + ro);
            }
#pragma unroll
            for (int mf = 0; mf < 2; ++mf)
#pragma unroll
                for (int nf = 0; nf < 8; ++nf) {
                    const uint32_t* bhp = &bh[nf >> 1][(nf & 1) * 2];
                    const uint32_t* blp = &bl[nf >> 1][(nf & 1) * 2];
                    float* d = acc[mf][nf];
                    mma16816(d, ah[mf], bhp[0], bhp[1]);             // Ah*Bh
                    if (TERMS == 3) mma16816(d, al[mf], bhp[0], bhp[1]); // Al*Bh
                    mma16816(d, ah[mf], blp[0], blp[1]);             // Ah*Bl
                }
        }
        __syncthreads();
    }

    int qrow = lane >> 2;
    int qcol = (lane & 3) * 2;
#pragma unroll
    for (int mf = 0; mf < 2; ++mf)
#pragma unroll
        for (int nf = 0; nf < 8; ++nf)
#pragma unroll
            for (int half = 0; half < 2; ++half) {
                int m = m0 + wm * 32 + mf * 16 + qrow + half * 8;
                int n = n0 + wn * 64 + nf * 8 + qcol;
                float v0 = acc[mf][nf][half * 2 + 0];
                float v1 = acc[mf][nf][half * 2 + 1];
                size_t off = (size_t)m * ldc + n;
                if (EPI <= 2) {
                    float b0 = 0.f, b1 = 0.f;
                    if (EPI == 1) { b0 = bias[n]; b1 = bias[n + 1]; }
                    if (EPI == 2) { b0 = bias[m]; b1 = bias[m]; }
                    __nv_bfloat16 h0, l0, h1, l1;
                    split2(v0 + b0, h0, l0);
                    split2(v1 + b1, h1, l1);
                    *(__nv_bfloat162*)((__nv_bfloat16*)C1 + bz * sC + off) =
                        __nv_bfloat162(h0, h1);
                    *(__nv_bfloat162*)((__nv_bfloat16*)C2 + bz * sC + off) =
                        __nv_bfloat162(l0, l1);
                } else if (EPI == 3) {
                    *(float2*)((float*)C1 + bz * sC + off) =
                        make_float2(v0 * alpha, v1 * alpha);
                } else {
                    float bm = bias[m];
                    const float* R = resid + bz * sR + off;
                    *(float2*)((float*)C1 + bz * sC + off) =
                        make_float2(v0 + bm + R[0], v1 + bm + R[1]);
                }
            }
}

// ---------------------------------------------------------------------------
// Launch
// ---------------------------------------------------------------------------
extern "C" void kernel_launch(void* const* d_in, const int* in_sizes, int n_in,
                              void* d_out, int out_size) {
    (void)in_sizes; (void)n_in; (void)out_size;
    const float* x     = (const float*)d_in[0];
    const float* gamma = (const float*)d_in[1];
    const float* beta  = (const float*)d_in[2];
    const float* wq    = (const float*)d_in[3];
    const float* bq    = (const float*)d_in[4];
    const float* wk    = (const float*)d_in[5];
    const float* bk    = (const float*)d_in[6];
    const float* wv    = (const float*)d_in[7];
    const float* bv    = (const float*)d_in[8];
    const float* wo    = (const float*)d_in[9];
    const float* bo    = (const float*)d_in[10];
    float* out = (float*)d_out;

    float *stats, *attn;
    __nv_bfloat16 *hTh, *hTl, *qTh, *qTl, *kTh, *kTl, *vh, *vl, *oTh, *oTl;
    __nv_bfloat16 *wqh, *wql, *wkh, *wkl, *wvh, *wvl, *woh, *wol, *Ph;
    cudaGetSymbolAddress((void**)&stats, g_stats);
    cudaGetSymbolAddress((void**)&attn,  g_attn);
    cudaGetSymbolAddress((void**)&hTh, g_hT_hi); cudaGetSymbolAddress((void**)&hTl, g_hT_lo);
    cudaGetSymbolAddress((void**)&qTh, g_qT_hi); cudaGetSymbolAddress((void**)&qTl, g_qT_lo);
    cudaGetSymbolAddress((void**)&kTh, g_kT_hi); cudaGetSymbolAddress((void**)&kTl, g_kT_lo);
    cudaGetSymbolAddress((void**)&vh,  g_v_hi);  cudaGetSymbolAddress((void**)&vl,  g_v_lo);
    cudaGetSymbolAddress((void**)&oTh, g_oT_hi); cudaGetSymbolAddress((void**)&oTl, g_oT_lo);
    cudaGetSymbolAddress((void**)&wqh, g_wq_hi); cudaGetSymbolAddress((void**)&wql, g_wq_lo);
    cudaGetSymbolAddress((void**)&wkh, g_wk_hi); cudaGetSymbolAddress((void**)&wkl, g_wk_lo);
    cudaGetSymbolAddress((void**)&wvh, g_wv_hi); cudaGetSymbolAddress((void**)&wvl, g_wv_lo);
    cudaGetSymbolAddress((void**)&woh, g_wo_hi); cudaGetSymbolAddress((void**)&wol, g_wo_lo);
    cudaGetSymbolAddress((void**)&Ph,  g_P_hi);

    cudaFuncSetAttribute(gemm5<0,2>, cudaFuncAttributeMaxDynamicSharedMemorySize, SMEMSZ);
    cudaFuncSetAttribute(gemm5<1,3>, cudaFuncAttributeMaxDynamicSharedMemorySize, SMEMSZ);
    cudaFuncSetAttribute(gemm5<2,3>, cudaFuncAttributeMaxDynamicSharedMemorySize, SMEMSZ);
    cudaFuncSetAttribute(gemm5<3,2>, cudaFuncAttributeMaxDynamicSharedMemorySize, SMEMSZ);
    cudaFuncSetAttribute(gemm5<4,3>, cudaFuncAttributeMaxDynamicSharedMemorySize, SMEMSZ);

    const size_t sCN = (size_t)C_ * NSP;
    const size_t sNN = (size_t)NSP * NSP;
    const float scale = 0.044194173824159216f;   // 512^-0.5

    // 1. GroupNorm (stats, then apply+transpose+split -> hT[p][c])
    gn_stats_kernel<<<B_ * NGR, 256>>>(x, stats);
    gn_apply_t_kernel<<<dim3(NSP / 32, C_ / 32, B_), dim3(32, 8)>>>(
        x, gamma, beta, stats, hTh, hTl);

    // 2. weight splits
    split_kernel<<<C_ * C_ / 1024, 256>>>(wq, wqh, wql, C_ * C_ / 4);
    split_kernel<<<C_ * C_ / 1024, 256>>>(wk, wkh, wkl, C_ * C_ / 4);
    split_kernel<<<C_ * C_ / 1024, 256>>>(wv, wvh, wvl, C_ * C_ / 4);
    split_kernel<<<C_ * C_ / 1024, 256>>>(wo, woh, wol, C_ * C_ / 4);

    // 3. qT[p][co] = hT[p][:] . Wq[co][:]  (M=4096,N=512,K=512) 3-term, +bias[n]
    dim3 gQ(C_ / BN, NSP / BM, B_);
    gemm5<1,3><<<gQ, 256, SMEMSZ>>>(hTh, hTl, wqh, wql, C_, C_, C_, sCN, 0,
                                    qTh, qTl, C_, sCN, bq, nullptr, 0, 1.f);
    gemm5<1,3><<<gQ, 256, SMEMSZ>>>(hTh, hTl, wkh, wkl, C_, C_, C_, sCN, 0,
                                    kTh, kTl, C_, sCN, bk, nullptr, 0, 1.f);
    // v[co][p] = Wv[co][:] . hT[p][:]  (M=512,N=4096,K=512) 3-term, +bias[m]
    dim3 gV(NSP / BN, C_ / BM, B_);
    gemm5<2,3><<<gV, 256, SMEMSZ>>>(wvh, wvl, hTh, hTl, C_, C_, C_, 0, sCN,
                                    vh, vl, NSP, sCN, bv, nullptr, 0, 1.f);

    // 4. attn[i][j] = scale * qh[i][:] . (kh+kl)[j][:]  (M=N=4096,K=512) 2-term
    dim3 gS(NSP / BN, NSP / BM, B_);
    gemm5<3,2><<<gS, 256, SMEMSZ>>>(qTh, nullptr, kTh, kTl, C_, C_, C_, sCN, sCN,
                                    attn, nullptr, NSP, sNN, nullptr, nullptr, 0, scale);

    // 5. softmax -> P hi only
    softmax_kernel<<<B_ * NSP, 256>>>(attn, Ph);

    // 6. oT[i][c] = Ph[i][:] . (vh+vl)[c][:]  (M=4096,N=512,K=4096) 2-term
    dim3 gO(C_ / BN, NSP / BM, B_);
    gemm5<0,2><<<gO, 256, SMEMSZ>>>(Ph, nullptr, vh, vl, NSP, NSP, NSP, sNN, sCN,
                                    oTh, oTl, C_, sCN, nullptr, nullptr, 0, 1.f);

    // 7. out[c][p] = x + bo[c] + Wo[c][:] . oT[p][:]  (M=512,N=4096,K=512) 3-term
    dim3 gF(NSP / BN, C_ / BM, B_);
    gemm5<4,3><<<gF, 256, SMEMSZ>>>(woh, wol, oTh, oTl, C_, C_, C_, 0, sCN,
                                    out, nullptr, NSP, sCN, bo, x, sCN, 1.f);
}